// round 15
// baseline (speedup 1.0000x reference)
#include <cuda_runtime.h>
#include <cuda_fp16.h>
#include <mma.h>
#include <cstdint>

using namespace nvcuda;

#define NV   100000
#define ME   50000
#define PP   1600000
#define C    128
#define NEG_SLOPE 0.2f
#define SCAN_B 1024
#define NBV   ((NV + SCAN_B - 1) / SCAN_B)    // 98
#define NBE   ((ME + SCAN_B - 1) / SCAN_B)    // 49

// ---------------- scratch (device globals; no allocations allowed) ----------
__device__ __half g_H16[(size_t)NV * C];     // H fp16
__device__ __half g_Edge[(size_t)ME * C];    // edge feature buffer (fp16, reused)
__device__ __half g_Vert[(size_t)NV * C];    // vertex buffer; first holds H*dvi
__device__ float g_s[NV];
__device__ float g_d[NV];
__device__ float g_inv_dv[NV];
__device__ float g_dvi[NV];                  // dv^-1/2
__device__ float g_inv_de[ME];
__device__ float g_alpha[PP];                // per-slot (CSR_v order) softmax weight
__device__ float g_uw[2 * C + 2];            // projected wsrc/wdst + consts

__device__ int  g_cnt_v[NV];
__device__ int  g_cnt_e[ME];
__device__ int  g_off_v[NV + 1];
__device__ int  g_off_e[ME + 1];
__device__ int  g_cur_v[NV];
__device__ int  g_cur_e[ME];
__device__ int2 g_csr_v_pack[PP];            // (edge id, src_v) per vertex-grouped slot
__device__ int  g_csr_e_src[PP];             // vertex id per edge-grouped slot
__device__ int  g_part_v[256];               // scan partials
__device__ int  g_part_e[256];

// ---------------- tensor-core GEMM: H16 = fp16(X W^T + b) -------------------
__global__ void gemm_wmma_kernel(const float* __restrict__ X,
                                 const float* __restrict__ W,
                                 const float* __restrict__ bias,
                                 __half* __restrict__ H16, int nrows) {
    extern __shared__ float sH[];            // 128*128 fp32 staging (64KB dynamic)
    __shared__ __half sX[128][40];
    __shared__ __half sW[128][40];
    __shared__ float  sB[128];

    const int tid = threadIdx.x;
    const int wid = tid >> 5;
    const int row0 = blockIdx.x * 128;
    const int warp_m = wid & 3;
    const int warp_n = wid >> 2;

    if (tid < 128) sB[tid] = bias[tid];

    wmma::fragment<wmma::accumulator, 16, 16, 16, float> acc[2][4];
#pragma unroll
    for (int i = 0; i < 2; i++)
#pragma unroll
        for (int j = 0; j < 4; j++) wmma::fill_fragment(acc[i][j], 0.f);

    const int lr = tid >> 1;
    const int lk = (tid & 1) * 16;

    for (int k0 = 0; k0 < C; k0 += 32) {
        {
            float4 v0, v1, v2, v3;
            int gr = row0 + lr;
            if (gr < nrows) {
                const float4* p = (const float4*)&X[(size_t)gr * C + k0 + lk];
                v0 = p[0]; v1 = p[1]; v2 = p[2]; v3 = p[3];
            } else {
                v0 = v1 = v2 = v3 = make_float4(0.f, 0.f, 0.f, 0.f);
            }
            __half2* d = (__half2*)&sX[lr][lk];
            d[0] = __floats2half2_rn(v0.x, v0.y); d[1] = __floats2half2_rn(v0.z, v0.w);
            d[2] = __floats2half2_rn(v1.x, v1.y); d[3] = __floats2half2_rn(v1.z, v1.w);
            d[4] = __floats2half2_rn(v2.x, v2.y); d[5] = __floats2half2_rn(v2.z, v2.w);
            d[6] = __floats2half2_rn(v3.x, v3.y); d[7] = __floats2half2_rn(v3.z, v3.w);
        }
        {
            const float4* p = (const float4*)&W[(size_t)lr * C + k0 + lk];
            float4 v0 = p[0], v1 = p[1], v2 = p[2], v3 = p[3];
            __half2* d = (__half2*)&sW[lr][lk];
            d[0] = __floats2half2_rn(v0.x, v0.y); d[1] = __floats2half2_rn(v0.z, v0.w);
            d[2] = __floats2half2_rn(v1.x, v1.y); d[3] = __floats2half2_rn(v1.z, v1.w);
            d[4] = __floats2half2_rn(v2.x, v2.y); d[5] = __floats2half2_rn(v2.z, v2.w);
            d[6] = __floats2half2_rn(v3.x, v3.y); d[7] = __floats2half2_rn(v3.z, v3.w);
        }
        __syncthreads();
#pragma unroll
        for (int ks = 0; ks < 32; ks += 16) {
            wmma::fragment<wmma::matrix_a, 16, 16, 16, __half, wmma::row_major> af[2];
            wmma::fragment<wmma::matrix_b, 16, 16, 16, __half, wmma::col_major> bf[4];
#pragma unroll
            for (int i = 0; i < 2; i++)
                wmma::load_matrix_sync(af[i], &sX[warp_m * 32 + i * 16][ks], 40);
#pragma unroll
            for (int j = 0; j < 4; j++)
                wmma::load_matrix_sync(bf[j], &sW[warp_n * 64 + j * 16][ks], 40);
#pragma unroll
            for (int i = 0; i < 2; i++)
#pragma unroll
                for (int j = 0; j < 4; j++)
                    wmma::mma_sync(acc[i][j], af[i], bf[j], acc[i][j]);
        }
        __syncthreads();
    }
#pragma unroll
    for (int i = 0; i < 2; i++)
#pragma unroll
        for (int j = 0; j < 4; j++)
            wmma::store_matrix_sync(&sH[(size_t)(warp_m * 32 + i * 16) * 128 +
                                        warp_n * 64 + j * 16],
                                    acc[i][j], 128, wmma::mem_row_major);
    __syncthreads();
#pragma unroll
    for (int it = 0; it < 8; it++) {
        int lin = it * 256 + tid;
        int r = lin >> 4;
        int seg = lin & 15;
        int gr = row0 + r;
        if (gr < nrows) {
            const float* src = &sH[(size_t)r * 128 + seg * 8];
            const float* bb = &sB[seg * 8];
            __half2 h0 = __floats2half2_rn(src[0] + bb[0], src[1] + bb[1]);
            __half2 h1 = __floats2half2_rn(src[2] + bb[2], src[3] + bb[3]);
            __half2 h2 = __floats2half2_rn(src[4] + bb[4], src[5] + bb[5]);
            __half2 h3 = __floats2half2_rn(src[6] + bb[6], src[7] + bb[7]);
            uint4 o;
            o.x = *(unsigned*)&h0; o.y = *(unsigned*)&h1;
            o.z = *(unsigned*)&h2; o.w = *(unsigned*)&h3;
            *(uint4*)&H16[(size_t)gr * C + seg * 8] = o;
        }
    }
}

// ---------------- prep: uw = W^T wsrc / W^T wdst + b dots --------------------
__global__ void prep_uw_kernel(const float* __restrict__ W,
                               const float* __restrict__ b,
                               const float* __restrict__ wsrc,
                               const float* __restrict__ wdst) {
    int k = threadIdx.x;
    float a = 0.f, c = 0.f;
#pragma unroll 8
    for (int j = 0; j < C; j++) {
        float wj = W[(size_t)j * C + k];
        a = fmaf(wj, wsrc[j], a);
        c = fmaf(wj, wdst[j], c);
    }
    g_uw[k] = a;
    g_uw[C + k] = c;
    if (k == 0) {
        float cs = 0.f, cd = 0.f;
        for (int j = 0; j < C; j++) { cs += b[j] * wsrc[j]; cd += b[j] * wdst[j]; }
        g_uw[2 * C] = cs;
        g_uw[2 * C + 1] = cd;
    }
}

// ---------------- s = X uws + cs, d = X uwd + cd (warp per row) -------------
__global__ void sd_kernel(const float* __restrict__ X,
                          float* __restrict__ s, float* __restrict__ d) {
    int w = (blockIdx.x * blockDim.x + threadIdx.x) >> 5;
    int lane = threadIdx.x & 31;
    if (w >= NV) return;
    float4 h = *(const float4*)&X[(size_t)w * C + lane * 4];
    float4 a = *(const float4*)&g_uw[lane * 4];
    float4 bb = *(const float4*)&g_uw[C + lane * 4];
    float ss = h.x * a.x + h.y * a.y + h.z * a.z + h.w * a.w;
    float dd = h.x * bb.x + h.y * bb.y + h.z * bb.z + h.w * bb.w;
#pragma unroll
    for (int o = 16; o; o >>= 1) {
        ss += __shfl_xor_sync(0xffffffffu, ss, o);
        dd += __shfl_xor_sync(0xffffffffu, dd, o);
    }
    if (lane == 0) { s[w] = ss + g_uw[2 * C]; d[w] = dd + g_uw[2 * C + 1]; }
}

// ---------------- Hs = H16 * dvi (sequential elementwise, fp16) -------------
__global__ void scaleH_kernel(const __half* __restrict__ H16,
                              __half* __restrict__ Hs) {
    int i = blockIdx.x * blockDim.x + threadIdx.x;      // uint4 index
    if (i >= NV * 16) return;
    float sc = g_dvi[i >> 4];
    uint4 r = __ldg(&((const uint4*)H16)[i]);
    float2 f0 = __half22float2(*(__half2*)&r.x);
    float2 f1 = __half22float2(*(__half2*)&r.y);
    float2 f2 = __half22float2(*(__half2*)&r.z);
    float2 f3 = __half22float2(*(__half2*)&r.w);
    __half2 o0 = __floats2half2_rn(f0.x * sc, f0.y * sc);
    __half2 o1 = __floats2half2_rn(f1.x * sc, f1.y * sc);
    __half2 o2 = __floats2half2_rn(f2.x * sc, f2.y * sc);
    __half2 o3 = __floats2half2_rn(f3.x * sc, f3.y * sc);
    uint4 o;
    o.x = *(unsigned*)&o0; o.y = *(unsigned*)&o1;
    o.z = *(unsigned*)&o2; o.w = *(unsigned*)&o3;
    ((uint4*)Hs)[i] = o;
}

// ---------------- CSR build: histogram, 4 pairs per thread ------------------
__global__ void hist_kernel4(const int4* __restrict__ pv4,
                             const int4* __restrict__ pe4) {
    int p = blockIdx.x * blockDim.x + threadIdx.x;
    if (p >= PP / 4) return;
    int4 v = __ldg(&pv4[p]);
    int4 e = __ldg(&pe4[p]);
    atomicAdd(&g_cnt_v[v.x], 1); atomicAdd(&g_cnt_v[v.y], 1);
    atomicAdd(&g_cnt_v[v.z], 1); atomicAdd(&g_cnt_v[v.w], 1);
    atomicAdd(&g_cnt_e[e.x], 1); atomicAdd(&g_cnt_e[e.y], 1);
    atomicAdd(&g_cnt_e[e.z], 1); atomicAdd(&g_cnt_e[e.w], 1);
}

// ---------------- merged 3-phase exclusive scan (V and E together) ----------
__global__ void scan_reduce_both() {
    __shared__ int wsum[32];
    int b = blockIdx.x;
    const int* in; int* part; int n; int bid;
    if (b < NBV) { in = g_cnt_v; part = g_part_v; n = NV; bid = b; }
    else         { in = g_cnt_e; part = g_part_e; n = ME; bid = b - NBV; }
    int i = bid * SCAN_B + threadIdx.x;
    int v = (i < n) ? in[i] : 0;
    int lane = threadIdx.x & 31, wid = threadIdx.x >> 5;
#pragma unroll
    for (int o = 16; o; o >>= 1) v += __shfl_xor_sync(0xffffffffu, v, o);
    if (lane == 0) wsum[wid] = v;
    __syncthreads();
    if (wid == 0) {
        int x = (lane < (SCAN_B >> 5)) ? wsum[lane] : 0;
#pragma unroll
        for (int o = 16; o; o >>= 1) x += __shfl_xor_sync(0xffffffffu, x, o);
        if (lane == 0) part[bid] = x;
    }
}
__global__ void scan_partials_both() {
    __shared__ int wsum[32];
    int* part; int nb;
    if (blockIdx.x == 0) { part = g_part_v; nb = NBV; }
    else                 { part = g_part_e; nb = NBE; }
    int tid = threadIdx.x, lane = tid & 31, wid = tid >> 5;
    int v = (tid < nb) ? part[tid] : 0;
    int x = v;
#pragma unroll
    for (int o = 1; o < 32; o <<= 1) {
        int t = __shfl_up_sync(0xffffffffu, x, o);
        if (lane >= o) x += t;
    }
    if (lane == 31) wsum[wid] = x;
    __syncthreads();
    if (wid == 0) {
        int w = (lane < 32) ? wsum[lane] : 0;
#pragma unroll
        for (int o = 1; o < 32; o <<= 1) {
            int t = __shfl_up_sync(0xffffffffu, w, o);
            if (lane >= o) w += t;
        }
        wsum[lane] = w;
    }
    __syncthreads();
    int off = (wid == 0) ? 0 : wsum[wid - 1];
    if (tid < nb) part[tid] = off + x - v;     // exclusive
}
__global__ void scan_apply_both() {
    __shared__ int wsum[32];
    int b = blockIdx.x;
    const int* in; const int* part; int* off; int* cur;
    float* invd; float* disqrt; int n; int bid;
    if (b < NBV) {
        in = g_cnt_v; part = g_part_v; off = g_off_v; cur = g_cur_v;
        invd = g_inv_dv; disqrt = g_dvi; n = NV; bid = b;
    } else {
        in = g_cnt_e; part = g_part_e; off = g_off_e; cur = g_cur_e;
        invd = g_inv_de; disqrt = nullptr; n = ME; bid = b - NBV;
    }
    int i = bid * SCAN_B + threadIdx.x;
    int lane = threadIdx.x & 31, wid = threadIdx.x >> 5;
    int v = (i < n) ? in[i] : 0;
    int x = v;
#pragma unroll
    for (int o = 1; o < 32; o <<= 1) {
        int t = __shfl_up_sync(0xffffffffu, x, o);
        if (lane >= o) x += t;
    }
    if (lane == 31) wsum[wid] = x;
    __syncthreads();
    if (wid == 0) {
        int w = (lane < (SCAN_B >> 5)) ? wsum[lane] : 0;
#pragma unroll
        for (int o = 1; o < 32; o <<= 1) {
            int t = __shfl_up_sync(0xffffffffu, w, o);
            if (lane >= o) w += t;
        }
        wsum[lane] = w;
    }
    __syncthreads();
    int woff = (wid == 0) ? 0 : wsum[wid - 1];
    if (i < n) {
        int val = part[bid] + woff + x - v;
        off[i] = val;
        cur[i] = val;
        float deg = (float)max(v, 1);
        invd[i] = 1.f / deg;
        if (disqrt) disqrt[i] = rsqrtf(deg);
    }
    if (i == 0) off[n] = PP;
}

// ---------------- CSR fill (packed v-side payload), 4 pairs per thread ------
__global__ void fill_kernel4(const int4* __restrict__ pv4,
                             const int4* __restrict__ pe4,
                             const int4* __restrict__ sv4) {
    int p = blockIdx.x * blockDim.x + threadIdx.x;
    if (p >= PP / 4) return;
    int4 v = __ldg(&pv4[p]);
    int4 e = __ldg(&pe4[p]);
    int4 s = __ldg(&sv4[p]);
    int sl;
    sl = atomicAdd(&g_cur_v[v.x], 1); g_csr_v_pack[sl] = make_int2(e.x, s.x);
    sl = atomicAdd(&g_cur_v[v.y], 1); g_csr_v_pack[sl] = make_int2(e.y, s.y);
    sl = atomicAdd(&g_cur_v[v.z], 1); g_csr_v_pack[sl] = make_int2(e.z, s.z);
    sl = atomicAdd(&g_cur_v[v.w], 1); g_csr_v_pack[sl] = make_int2(e.w, s.w);
    sl = atomicAdd(&g_cur_e[e.x], 1); g_csr_e_src[sl] = v.x;
    sl = atomicAdd(&g_cur_e[e.y], 1); g_csr_e_src[sl] = v.y;
    sl = atomicAdd(&g_cur_e[e.z], 1); g_csr_e_src[sl] = v.z;
    sl = atomicAdd(&g_cur_e[e.w], 1); g_csr_e_src[sl] = v.w;
}

// ---------------- softmax: warp per vertex, register-cached scores ----------
__device__ __forceinline__ float slot_score(const float* s, int i, float dval) {
    float x = __ldg(&s[g_csr_v_pack[i].y]) + dval;
    x = x > 0.f ? x : NEG_SLOPE * x;
    return fminf(fmaxf(x, 0.001f), 5.0f);
}

__global__ void softmax_kernel(const float* __restrict__ s,
                               const float* __restrict__ d) {
    int v = blockIdx.x * (blockDim.x >> 5) + (threadIdx.x >> 5);
    if (v >= NV) return;
    int lane = threadIdx.x & 31;
    int beg = g_off_v[v], end = g_off_v[v + 1];
    int n = end - beg;
    if (n == 0) return;
    float dval = __ldg(&d[v]);
    if (n <= 128) {
        float sc[4];
        int k = 0;
        float mx = -1e30f;
        for (int i = beg + lane; i < end; i += 32, k++) {
            sc[k] = slot_score(s, i, dval);
            mx = fmaxf(mx, sc[k]);
        }
#pragma unroll
        for (int o = 16; o; o >>= 1) mx = fmaxf(mx, __shfl_xor_sync(0xffffffffu, mx, o));
        float sum = 0.f;
        k = 0;
        for (int i = beg + lane; i < end; i += 32, k++) {
            sc[k] = __expf(sc[k] - mx);
            sum += sc[k];
        }
#pragma unroll
        for (int o = 16; o; o >>= 1) sum += __shfl_xor_sync(0xffffffffu, sum, o);
        float inv = 1.f / sum;
        k = 0;
        for (int i = beg + lane; i < end; i += 32, k++)
            g_alpha[i] = sc[k] * inv;
    } else {
        float mx = -1e30f;
        for (int i = beg + lane; i < end; i += 32) {
            float x = slot_score(s, i, dval);
            g_alpha[i] = x;
            mx = fmaxf(mx, x);
        }
#pragma unroll
        for (int o = 16; o; o >>= 1) mx = fmaxf(mx, __shfl_xor_sync(0xffffffffu, mx, o));
        float sum = 0.f;
        for (int i = beg + lane; i < end; i += 32) {
            float e = __expf(g_alpha[i] - mx);
            g_alpha[i] = e;
            sum += e;
        }
#pragma unroll
        for (int o = 16; o; o >>= 1) sum += __shfl_xor_sync(0xffffffffu, sum, o);
        float inv = 1.f / sum;
        for (int i = beg + lane; i < end; i += 32)
            g_alpha[i] *= inv;
    }
}

// ---------------- CSR gather segment-sum, fp16 rows -------------------------
template<bool IDX2, bool PAIRW, bool FINAL>
__global__ void gather_kernel(const __half* __restrict__ src,
                              void* __restrict__ dstv,
                              const void* __restrict__ csrv,
                              const int* __restrict__ off,
                              const float* __restrict__ pw,
                              const float* __restrict__ oscale,
                              int nrows) {
    int row = blockIdx.x * (blockDim.x >> 5) + (threadIdx.x >> 5);
    if (row >= nrows) return;
    int lane = threadIdx.x & 31;
    int half = lane >> 4;
    int hl = lane & 15;
    int beg = __ldg(&off[row]), end = __ldg(&off[row + 1]);
    const uint4* s4 = (const uint4*)src;
    const int*  csr1 = (const int*)csrv;
    const int2* csr2 = (const int2*)csrv;
    float acc[8];
#pragma unroll
    for (int c = 0; c < 8; c++) acc[c] = 0.f;

    int i = beg;
    for (; i + 8 <= end; i += 8) {
        int idx[4]; float w[4]; uint4 r[4];
#pragma unroll
        for (int u = 0; u < 4; u++)
            idx[u] = IDX2 ? __ldg(&csr2[i + 2 * u + half]).x
                          : __ldg(&csr1[i + 2 * u + half]);
#pragma unroll
        for (int u = 0; u < 4; u++)
            w[u] = PAIRW ? __ldg(&pw[i + 2 * u + half]) : 1.f;
#pragma unroll
        for (int u = 0; u < 4; u++) r[u] = __ldg(&s4[(size_t)idx[u] * 16 + hl]);
#pragma unroll
        for (int u = 0; u < 4; u++) {
            float2 f0 = __half22float2(*(__half2*)&r[u].x);
            float2 f1 = __half22float2(*(__half2*)&r[u].y);
            float2 f2 = __half22float2(*(__half2*)&r[u].z);
            float2 f3 = __half22float2(*(__half2*)&r[u].w);
            if (PAIRW) {
                acc[0] = fmaf(w[u], f0.x, acc[0]); acc[1] = fmaf(w[u], f0.y, acc[1]);
                acc[2] = fmaf(w[u], f1.x, acc[2]); acc[3] = fmaf(w[u], f1.y, acc[3]);
                acc[4] = fmaf(w[u], f2.x, acc[4]); acc[5] = fmaf(w[u], f2.y, acc[5]);
                acc[6] = fmaf(w[u], f3.x, acc[6]); acc[7] = fmaf(w[u], f3.y, acc[7]);
            } else {
                acc[0] += f0.x; acc[1] += f0.y; acc[2] += f1.x; acc[3] += f1.y;
                acc[4] += f2.x; acc[5] += f2.y; acc[6] += f3.x; acc[7] += f3.y;
            }
        }
    }
    for (; i < end; i += 2) {
        int j = i + half;
        if (j < end) {
            int idx = IDX2 ? __ldg(&csr2[j]).x : __ldg(&csr1[j]);
            float w = PAIRW ? __ldg(&pw[j]) : 1.f;
            uint4 r = __ldg(&s4[(size_t)idx * 16 + hl]);
            float2 f0 = __half22float2(*(__half2*)&r.x);
            float2 f1 = __half22float2(*(__half2*)&r.y);
            float2 f2 = __half22float2(*(__half2*)&r.z);
            float2 f3 = __half22float2(*(__half2*)&r.w);
            acc[0] = fmaf(w, f0.x, acc[0]); acc[1] = fmaf(w, f0.y, acc[1]);
            acc[2] = fmaf(w, f1.x, acc[2]); acc[3] = fmaf(w, f1.y, acc[3]);
            acc[4] = fmaf(w, f2.x, acc[4]); acc[5] = fmaf(w, f2.y, acc[5]);
            acc[6] = fmaf(w, f3.x, acc[6]); acc[7] = fmaf(w, f3.y, acc[7]);
        }
    }
#pragma unroll
    for (int c = 0; c < 8; c++)
        acc[c] += __shfl_xor_sync(0xffffffffu, acc[c], 16);

    float os = oscale ? __ldg(&oscale[row]) : 1.f;
#pragma unroll
    for (int c = 0; c < 8; c++) acc[c] *= os;

    if (lane < 16) {
        if (FINAL) {
#pragma unroll
            for (int c = 0; c < 8; c++)
                acc[c] = acc[c] > 0.f ? acc[c] : expm1f(acc[c]);
            float* o = (float*)dstv + (size_t)row * C + hl * 8;
            *(float4*)o       = make_float4(acc[0], acc[1], acc[2], acc[3]);
            *(float4*)(o + 4) = make_float4(acc[4], acc[5], acc[6], acc[7]);
        } else {
            __half2 h0 = __floats2half2_rn(acc[0], acc[1]);
            __half2 h1 = __floats2half2_rn(acc[2], acc[3]);
            __half2 h2 = __floats2half2_rn(acc[4], acc[5]);
            __half2 h3 = __floats2half2_rn(acc[6], acc[7]);
            uint4 o;
            o.x = *(unsigned*)&h0; o.y = *(unsigned*)&h1;
            o.z = *(unsigned*)&h2; o.w = *(unsigned*)&h3;
            ((uint4*)dstv)[(size_t)row * 16 + hl] = o;
        }
    }
}

// ---------------- launch ------------------------------------------------------
extern "C" void kernel_launch(void* const* d_in, const int* in_sizes, int n_in,
                              void* d_out, int out_size) {
    const float* X      = (const float*)d_in[0];
    const int*   pair_v = (const int*)d_in[1];
    const int*   pair_e = (const int*)d_in[2];
    const int*   src_v  = (const int*)d_in[3];
    const float* Wt     = (const float*)d_in[4];
    const float* bt     = (const float*)d_in[5];
    const float* wsrc   = (const float*)d_in[6];
    const float* wdst   = (const float*)d_in[7];
    float* out = (float*)d_out;

    void *pH16, *pE, *pV, *ps, *pd, *pcv, *pce, *pov, *poe;
    void *pdvi, *pinvde, *pinvdv, *palpha, *pcsrvp, *pcsres;
    cudaGetSymbolAddress(&pH16, g_H16);
    cudaGetSymbolAddress(&pE,   g_Edge);
    cudaGetSymbolAddress(&pV,   g_Vert);
    cudaGetSymbolAddress(&ps,   g_s);
    cudaGetSymbolAddress(&pd,   g_d);
    cudaGetSymbolAddress(&pcv,  g_cnt_v);
    cudaGetSymbolAddress(&pce,  g_cnt_e);
    cudaGetSymbolAddress(&pov,  g_off_v);
    cudaGetSymbolAddress(&poe,  g_off_e);
    cudaGetSymbolAddress(&pdvi,   g_dvi);
    cudaGetSymbolAddress(&pinvde, g_inv_de);
    cudaGetSymbolAddress(&pinvdv, g_inv_dv);
    cudaGetSymbolAddress(&palpha, g_alpha);
    cudaGetSymbolAddress(&pcsrvp, g_csr_v_pack);
    cudaGetSymbolAddress(&pcsres, g_csr_e_src);

    const __half* H16    = (const __half*)pH16;
    __half*       Ebuf   = (__half*)pE;
    __half*       Vbuf   = (__half*)pV;
    const float*  dvi    = (const float*)pdvi;
    const float*  inv_de = (const float*)pinvde;
    const float*  inv_dv = (const float*)pinvdv;
    const float*  alpha  = (const float*)palpha;
    const int*    off_v  = (const int*)pov;
    const int*    off_e  = (const int*)poe;

    const int TB = 256;
    const int WPB = TB / 32;
    const int pair4Blocks = (PP / 4 + TB - 1) / TB;
    const int gemmBlocks = (NV + 127) / 128;
    const int eRowBlocks = (ME + WPB - 1) / WPB;
    const int vRowBlocks = (NV + WPB - 1) / WPB;
    const int scaleBlocks = (NV * 16 + TB - 1) / TB;

    // ---- one-time stream/event setup (host resources only; no device mem) ----
    static cudaStream_t sA = nullptr, sB = nullptr;
    static cudaEvent_t ev0 = nullptr, evScan = nullptr, evSD = nullptr,
                       evA = nullptr, evF = nullptr, evS = nullptr, evB = nullptr;
    if (sA == nullptr) {
        cudaStreamCreateWithFlags(&sA, cudaStreamNonBlocking);
        cudaStreamCreateWithFlags(&sB, cudaStreamNonBlocking);
        cudaEventCreateWithFlags(&ev0,    cudaEventDisableTiming);
        cudaEventCreateWithFlags(&evScan, cudaEventDisableTiming);
        cudaEventCreateWithFlags(&evSD,   cudaEventDisableTiming);
        cudaEventCreateWithFlags(&evA,    cudaEventDisableTiming);
        cudaEventCreateWithFlags(&evF,    cudaEventDisableTiming);
        cudaEventCreateWithFlags(&evS,    cudaEventDisableTiming);
        cudaEventCreateWithFlags(&evB,    cudaEventDisableTiming);
        cudaFuncSetAttribute(gemm_wmma_kernel,
                             cudaFuncAttributeMaxDynamicSharedMemorySize, 65536);
    }

    // ---- fork: chain A (GEMM + s,d) on sA --------------------------------------
    cudaEventRecord(ev0, 0);
    cudaStreamWaitEvent(sA, ev0, 0);
    prep_uw_kernel<<<1, C, 0, sA>>>(Wt, bt, wsrc, wdst);
    gemm_wmma_kernel<<<gemmBlocks, TB, 65536, sA>>>(X, Wt, bt, (__half*)pH16, NV);
    sd_kernel<<<(NV * 32 + TB - 1) / TB, TB, 0, sA>>>(X, (float*)ps, (float*)pd);
    cudaEventRecord(evSD, sA);

    // ---- chain B (CSR build) on capture stream ---------------------------------
    cudaMemsetAsync(pcv, 0, NV * sizeof(int));
    cudaMemsetAsync(pce, 0, ME * sizeof(int));
    hist_kernel4<<<pair4Blocks, TB>>>((const int4*)pair_v, (const int4*)pair_e);
    scan_reduce_both<<<NBV + NBE, SCAN_B>>>();
    scan_partials_both<<<2, SCAN_B>>>();
    scan_apply_both<<<NBV + NBE, SCAN_B>>>();
    cudaEventRecord(evScan, 0);
    fill_kernel4<<<pair4Blocks, TB>>>((const int4*)pair_v, (const int4*)pair_e,
                                      (const int4*)src_v);
    cudaEventRecord(evF, 0);

    // ---- sA tail: Vbuf = H16 * dvi (needs GEMM + scan); overlaps fill ----------
    cudaStreamWaitEvent(sA, evScan, 0);
    scaleH_kernel<<<scaleBlocks, TB, 0, sA>>>(H16, Vbuf);
    cudaEventRecord(evA, sA);

    // ---- sB: P1..P3 need fill + scaled H ----------------------------------------
    cudaStreamWaitEvent(sB, evF, 0);
    cudaStreamWaitEvent(sB, evA, 0);
    // P1: Edge = Xe = inv_de * segsum_e( Hs[v] )   (Hs = H*dvi in Vbuf)
    gather_kernel<false, false, false><<<eRowBlocks, TB, 0, sB>>>(
        Vbuf, Ebuf, pcsres, off_e, nullptr, inv_de, ME);
    // P2: Vert = Hs' = dvi[v] * segsum_v( Edge[e] )   (overwrites Vbuf, after P1)
    gather_kernel<true, false, false><<<vRowBlocks, TB, 0, sB>>>(
        Ebuf, Vbuf, pcsrvp, off_v, nullptr, dvi, NV);
    // P3: Edge = Xe1 = inv_de * segsum_e( Vert[v] )
    gather_kernel<false, false, false><<<eRowBlocks, TB, 0, sB>>>(
        Vbuf, Ebuf, pcsres, off_e, nullptr, inv_de, ME);

    // ---- capture stream: softmax (after fill in-order; needs s,d) — overlaps P1-P3
    cudaStreamWaitEvent(0, evSD, 0);
    softmax_kernel<<<vRowBlocks, TB>>>((const float*)ps, (const float*)pd);
    cudaEventRecord(evS, 0);

    // ---- sB: P4..P6 (P4 needs alpha) --------------------------------------------
    cudaStreamWaitEvent(sB, evS, 0);
    // P4: Vert = Xv1 = segsum_v( alpha_slot * Edge[e] )
    gather_kernel<true, true, false><<<vRowBlocks, TB, 0, sB>>>(
        Ebuf, Vbuf, pcsrvp, off_v, alpha, nullptr, NV);
    // P5: Edge = Xe2 = inv_de * segsum_e( Vert[v] )
    gather_kernel<false, false, false><<<eRowBlocks, TB, 0, sB>>>(
        Vbuf, Ebuf, pcsres, off_e, nullptr, inv_de, ME);
    // P6: out = elu( inv_dv * segsum_v( Edge[e] ) )  (fp32 out)
    gather_kernel<true, false, true><<<vRowBlocks, TB, 0, sB>>>(
        Ebuf, out, pcsrvp, off_v, nullptr, inv_dv, NV);
    cudaEventRecord(evB, sB);

    // ---- join --------------------------------------------------------------------
    cudaStreamWaitEvent(0, evB, 0);
}

// round 16
// speedup vs baseline: 1.0368x; 1.0368x over previous
#include <cuda_runtime.h>
#include <cuda_fp16.h>
#include <mma.h>
#include <cstdint>

using namespace nvcuda;

#define NV   100000
#define ME   50000
#define PP   1600000
#define C    128
#define NEG_SLOPE 0.2f
#define SCAN_B 1024
#define NBV   ((NV + SCAN_B - 1) / SCAN_B)    // 98
#define NBE   ((ME + SCAN_B - 1) / SCAN_B)    // 49

// ---------------- scratch (device globals; no allocations allowed) ----------
__device__ __half g_H16[(size_t)NV * C];     // H fp16 (gather source)
__device__ __half g_Edge[(size_t)ME * C];    // edge feature buffer (fp16, reused)
__device__ __half g_Vert[(size_t)NV * C];    // vertex feature buffer (fp16, reused)
__device__ float g_s[NV];
__device__ float g_d[NV];
__device__ float g_inv_dv[NV];
__device__ float g_dvi[NV];                  // dv^-1/2
__device__ float g_inv_de[ME];
__device__ float g_alpha[PP];                // per-slot (CSR_v order) softmax weight
__device__ float g_uw[2 * C + 2];            // projected wsrc/wdst + consts

__device__ int  g_cnt_v[NV];
__device__ int  g_cnt_e[ME];
__device__ int  g_off_v[NV + 1];
__device__ int  g_off_e[ME + 1];
__device__ int  g_cur_v[NV];
__device__ int  g_cur_e[ME];
__device__ int2 g_csr_v_pack[PP];            // (edge id, src_v) per vertex-grouped slot
__device__ int  g_csr_e_src[PP];             // vertex id per edge-grouped slot
__device__ int  g_part_v[256];               // scan partials
__device__ int  g_part_e[256];

// ---------------- tensor-core GEMM: H16 = fp16(X W^T + b) -------------------
__global__ void gemm_wmma_kernel(const float* __restrict__ X,
                                 const float* __restrict__ W,
                                 const float* __restrict__ bias,
                                 __half* __restrict__ H16, int nrows) {
    extern __shared__ float sH[];            // 128*128 fp32 staging (64KB dynamic)
    __shared__ __half sX[128][40];
    __shared__ __half sW[128][40];
    __shared__ float  sB[128];

    const int tid = threadIdx.x;
    const int wid = tid >> 5;
    const int row0 = blockIdx.x * 128;
    const int warp_m = wid & 3;
    const int warp_n = wid >> 2;

    if (tid < 128) sB[tid] = bias[tid];

    wmma::fragment<wmma::accumulator, 16, 16, 16, float> acc[2][4];
#pragma unroll
    for (int i = 0; i < 2; i++)
#pragma unroll
        for (int j = 0; j < 4; j++) wmma::fill_fragment(acc[i][j], 0.f);

    const int lr = tid >> 1;
    const int lk = (tid & 1) * 16;

    for (int k0 = 0; k0 < C; k0 += 32) {
        {
            float4 v0, v1, v2, v3;
            int gr = row0 + lr;
            if (gr < nrows) {
                const float4* p = (const float4*)&X[(size_t)gr * C + k0 + lk];
                v0 = p[0]; v1 = p[1]; v2 = p[2]; v3 = p[3];
            } else {
                v0 = v1 = v2 = v3 = make_float4(0.f, 0.f, 0.f, 0.f);
            }
            __half2* d = (__half2*)&sX[lr][lk];
            d[0] = __floats2half2_rn(v0.x, v0.y); d[1] = __floats2half2_rn(v0.z, v0.w);
            d[2] = __floats2half2_rn(v1.x, v1.y); d[3] = __floats2half2_rn(v1.z, v1.w);
            d[4] = __floats2half2_rn(v2.x, v2.y); d[5] = __floats2half2_rn(v2.z, v2.w);
            d[6] = __floats2half2_rn(v3.x, v3.y); d[7] = __floats2half2_rn(v3.z, v3.w);
        }
        {
            const float4* p = (const float4*)&W[(size_t)lr * C + k0 + lk];
            float4 v0 = p[0], v1 = p[1], v2 = p[2], v3 = p[3];
            __half2* d = (__half2*)&sW[lr][lk];
            d[0] = __floats2half2_rn(v0.x, v0.y); d[1] = __floats2half2_rn(v0.z, v0.w);
            d[2] = __floats2half2_rn(v1.x, v1.y); d[3] = __floats2half2_rn(v1.z, v1.w);
            d[4] = __floats2half2_rn(v2.x, v2.y); d[5] = __floats2half2_rn(v2.z, v2.w);
            d[6] = __floats2half2_rn(v3.x, v3.y); d[7] = __floats2half2_rn(v3.z, v3.w);
        }
        __syncthreads();
#pragma unroll
        for (int ks = 0; ks < 32; ks += 16) {
            wmma::fragment<wmma::matrix_a, 16, 16, 16, __half, wmma::row_major> af[2];
            wmma::fragment<wmma::matrix_b, 16, 16, 16, __half, wmma::col_major> bf[4];
#pragma unroll
            for (int i = 0; i < 2; i++)
                wmma::load_matrix_sync(af[i], &sX[warp_m * 32 + i * 16][ks], 40);
#pragma unroll
            for (int j = 0; j < 4; j++)
                wmma::load_matrix_sync(bf[j], &sW[warp_n * 64 + j * 16][ks], 40);
#pragma unroll
            for (int i = 0; i < 2; i++)
#pragma unroll
                for (int j = 0; j < 4; j++)
                    wmma::mma_sync(acc[i][j], af[i], bf[j], acc[i][j]);
        }
        __syncthreads();
    }
#pragma unroll
    for (int i = 0; i < 2; i++)
#pragma unroll
        for (int j = 0; j < 4; j++)
            wmma::store_matrix_sync(&sH[(size_t)(warp_m * 32 + i * 16) * 128 +
                                        warp_n * 64 + j * 16],
                                    acc[i][j], 128, wmma::mem_row_major);
    __syncthreads();
#pragma unroll
    for (int it = 0; it < 8; it++) {
        int lin = it * 256 + tid;
        int r = lin >> 4;
        int seg = lin & 15;
        int gr = row0 + r;
        if (gr < nrows) {
            const float* src = &sH[(size_t)r * 128 + seg * 8];
            const float* bb = &sB[seg * 8];
            __half2 h0 = __floats2half2_rn(src[0] + bb[0], src[1] + bb[1]);
            __half2 h1 = __floats2half2_rn(src[2] + bb[2], src[3] + bb[3]);
            __half2 h2 = __floats2half2_rn(src[4] + bb[4], src[5] + bb[5]);
            __half2 h3 = __floats2half2_rn(src[6] + bb[6], src[7] + bb[7]);
            uint4 o;
            o.x = *(unsigned*)&h0; o.y = *(unsigned*)&h1;
            o.z = *(unsigned*)&h2; o.w = *(unsigned*)&h3;
            *(uint4*)&H16[(size_t)gr * C + seg * 8] = o;
        }
    }
}

// ---------------- prep: uw = W^T wsrc / W^T wdst + b dots --------------------
__global__ void prep_uw_kernel(const float* __restrict__ W,
                               const float* __restrict__ b,
                               const float* __restrict__ wsrc,
                               const float* __restrict__ wdst) {
    int k = threadIdx.x;
    float a = 0.f, c = 0.f;
#pragma unroll 8
    for (int j = 0; j < C; j++) {
        float wj = W[(size_t)j * C + k];
        a = fmaf(wj, wsrc[j], a);
        c = fmaf(wj, wdst[j], c);
    }
    g_uw[k] = a;
    g_uw[C + k] = c;
    if (k == 0) {
        float cs = 0.f, cd = 0.f;
        for (int j = 0; j < C; j++) { cs += b[j] * wsrc[j]; cd += b[j] * wdst[j]; }
        g_uw[2 * C] = cs;
        g_uw[2 * C + 1] = cd;
    }
}

// ---------------- s = X uws + cs, d = X uwd + cd (warp per row) -------------
__global__ void sd_kernel(const float* __restrict__ X,
                          float* __restrict__ s, float* __restrict__ d) {
    int w = (blockIdx.x * blockDim.x + threadIdx.x) >> 5;
    int lane = threadIdx.x & 31;
    if (w >= NV) return;
    float4 h = *(const float4*)&X[(size_t)w * C + lane * 4];
    float4 a = *(const float4*)&g_uw[lane * 4];
    float4 bb = *(const float4*)&g_uw[C + lane * 4];
    float ss = h.x * a.x + h.y * a.y + h.z * a.z + h.w * a.w;
    float dd = h.x * bb.x + h.y * bb.y + h.z * bb.z + h.w * bb.w;
#pragma unroll
    for (int o = 16; o; o >>= 1) {
        ss += __shfl_xor_sync(0xffffffffu, ss, o);
        dd += __shfl_xor_sync(0xffffffffu, dd, o);
    }
    if (lane == 0) { s[w] = ss + g_uw[2 * C]; d[w] = dd + g_uw[2 * C + 1]; }
}

// ---------------- CSR build: histogram, 4 pairs per thread ------------------
__global__ void hist_kernel4(const int4* __restrict__ pv4,
                             const int4* __restrict__ pe4) {
    int p = blockIdx.x * blockDim.x + threadIdx.x;
    if (p >= PP / 4) return;
    int4 v = __ldg(&pv4[p]);
    int4 e = __ldg(&pe4[p]);
    atomicAdd(&g_cnt_v[v.x], 1); atomicAdd(&g_cnt_v[v.y], 1);
    atomicAdd(&g_cnt_v[v.z], 1); atomicAdd(&g_cnt_v[v.w], 1);
    atomicAdd(&g_cnt_e[e.x], 1); atomicAdd(&g_cnt_e[e.y], 1);
    atomicAdd(&g_cnt_e[e.z], 1); atomicAdd(&g_cnt_e[e.w], 1);
}

// ---------------- merged 3-phase exclusive scan (V and E together) ----------
__global__ void scan_reduce_both() {
    __shared__ int wsum[32];
    int b = blockIdx.x;
    const int* in; int* part; int n; int bid;
    if (b < NBV) { in = g_cnt_v; part = g_part_v; n = NV; bid = b; }
    else         { in = g_cnt_e; part = g_part_e; n = ME; bid = b - NBV; }
    int i = bid * SCAN_B + threadIdx.x;
    int v = (i < n) ? in[i] : 0;
    int lane = threadIdx.x & 31, wid = threadIdx.x >> 5;
#pragma unroll
    for (int o = 16; o; o >>= 1) v += __shfl_xor_sync(0xffffffffu, v, o);
    if (lane == 0) wsum[wid] = v;
    __syncthreads();
    if (wid == 0) {
        int x = (lane < (SCAN_B >> 5)) ? wsum[lane] : 0;
#pragma unroll
        for (int o = 16; o; o >>= 1) x += __shfl_xor_sync(0xffffffffu, x, o);
        if (lane == 0) part[bid] = x;
    }
}
__global__ void scan_partials_both() {
    __shared__ int wsum[32];
    int* part; int nb;
    if (blockIdx.x == 0) { part = g_part_v; nb = NBV; }
    else                 { part = g_part_e; nb = NBE; }
    int tid = threadIdx.x, lane = tid & 31, wid = tid >> 5;
    int v = (tid < nb) ? part[tid] : 0;
    int x = v;
#pragma unroll
    for (int o = 1; o < 32; o <<= 1) {
        int t = __shfl_up_sync(0xffffffffu, x, o);
        if (lane >= o) x += t;
    }
    if (lane == 31) wsum[wid] = x;
    __syncthreads();
    if (wid == 0) {
        int w = (lane < 32) ? wsum[lane] : 0;
#pragma unroll
        for (int o = 1; o < 32; o <<= 1) {
            int t = __shfl_up_sync(0xffffffffu, w, o);
            if (lane >= o) w += t;
        }
        wsum[lane] = w;
    }
    __syncthreads();
    int off = (wid == 0) ? 0 : wsum[wid - 1];
    if (tid < nb) part[tid] = off + x - v;     // exclusive
}
__global__ void scan_apply_both() {
    __shared__ int wsum[32];
    int b = blockIdx.x;
    const int* in; const int* part; int* off; int* cur;
    float* invd; float* disqrt; int n; int bid;
    if (b < NBV) {
        in = g_cnt_v; part = g_part_v; off = g_off_v; cur = g_cur_v;
        invd = g_inv_dv; disqrt = g_dvi; n = NV; bid = b;
    } else {
        in = g_cnt_e; part = g_part_e; off = g_off_e; cur = g_cur_e;
        invd = g_inv_de; disqrt = nullptr; n = ME; bid = b - NBV;
    }
    int i = bid * SCAN_B + threadIdx.x;
    int lane = threadIdx.x & 31, wid = threadIdx.x >> 5;
    int v = (i < n) ? in[i] : 0;
    int x = v;
#pragma unroll
    for (int o = 1; o < 32; o <<= 1) {
        int t = __shfl_up_sync(0xffffffffu, x, o);
        if (lane >= o) x += t;
    }
    if (lane == 31) wsum[wid] = x;
    __syncthreads();
    if (wid == 0) {
        int w = (lane < (SCAN_B >> 5)) ? wsum[lane] : 0;
#pragma unroll
        for (int o = 1; o < 32; o <<= 1) {
            int t = __shfl_up_sync(0xffffffffu, w, o);
            if (lane >= o) w += t;
        }
        wsum[lane] = w;
    }
    __syncthreads();
    int woff = (wid == 0) ? 0 : wsum[wid - 1];
    if (i < n) {
        int val = part[bid] + woff + x - v;
        off[i] = val;
        cur[i] = val;
        float deg = (float)max(v, 1);
        invd[i] = 1.f / deg;
        if (disqrt) disqrt[i] = rsqrtf(deg);
    }
    if (i == 0) off[n] = PP;
}

// ---------------- CSR fill (packed v-side payload), 4 pairs per thread ------
__global__ void fill_kernel4(const int4* __restrict__ pv4,
                             const int4* __restrict__ pe4,
                             const int4* __restrict__ sv4) {
    int p = blockIdx.x * blockDim.x + threadIdx.x;
    if (p >= PP / 4) return;
    int4 v = __ldg(&pv4[p]);
    int4 e = __ldg(&pe4[p]);
    int4 s = __ldg(&sv4[p]);
    int sl;
    sl = atomicAdd(&g_cur_v[v.x], 1); g_csr_v_pack[sl] = make_int2(e.x, s.x);
    sl = atomicAdd(&g_cur_v[v.y], 1); g_csr_v_pack[sl] = make_int2(e.y, s.y);
    sl = atomicAdd(&g_cur_v[v.z], 1); g_csr_v_pack[sl] = make_int2(e.z, s.z);
    sl = atomicAdd(&g_cur_v[v.w], 1); g_csr_v_pack[sl] = make_int2(e.w, s.w);
    sl = atomicAdd(&g_cur_e[e.x], 1); g_csr_e_src[sl] = v.x;
    sl = atomicAdd(&g_cur_e[e.y], 1); g_csr_e_src[sl] = v.y;
    sl = atomicAdd(&g_cur_e[e.z], 1); g_csr_e_src[sl] = v.z;
    sl = atomicAdd(&g_cur_e[e.w], 1); g_csr_e_src[sl] = v.w;
}

// ---------------- softmax: warp per vertex, register-cached scores ----------
__device__ __forceinline__ float slot_score(const float* s, int i, float dval) {
    float x = __ldg(&s[g_csr_v_pack[i].y]) + dval;
    x = x > 0.f ? x : NEG_SLOPE * x;
    return fminf(fmaxf(x, 0.001f), 5.0f);
}

__global__ void softmax_kernel(const float* __restrict__ s,
                               const float* __restrict__ d) {
    int v = blockIdx.x * (blockDim.x >> 5) + (threadIdx.x >> 5);
    if (v >= NV) return;
    int lane = threadIdx.x & 31;
    int beg = g_off_v[v], end = g_off_v[v + 1];
    int n = end - beg;
    if (n == 0) return;
    float dval = __ldg(&d[v]);
    if (n <= 128) {
        float sc[4];
        int k = 0;
        float mx = -1e30f;
        for (int i = beg + lane; i < end; i += 32, k++) {
            sc[k] = slot_score(s, i, dval);
            mx = fmaxf(mx, sc[k]);
        }
#pragma unroll
        for (int o = 16; o; o >>= 1) mx = fmaxf(mx, __shfl_xor_sync(0xffffffffu, mx, o));
        float sum = 0.f;
        k = 0;
        for (int i = beg + lane; i < end; i += 32, k++) {
            sc[k] = __expf(sc[k] - mx);
            sum += sc[k];
        }
#pragma unroll
        for (int o = 16; o; o >>= 1) sum += __shfl_xor_sync(0xffffffffu, sum, o);
        float inv = 1.f / sum;
        k = 0;
        for (int i = beg + lane; i < end; i += 32, k++)
            g_alpha[i] = sc[k] * inv;
    } else {
        float mx = -1e30f;
        for (int i = beg + lane; i < end; i += 32) {
            float x = slot_score(s, i, dval);
            g_alpha[i] = x;
            mx = fmaxf(mx, x);
        }
#pragma unroll
        for (int o = 16; o; o >>= 1) mx = fmaxf(mx, __shfl_xor_sync(0xffffffffu, mx, o));
        float sum = 0.f;
        for (int i = beg + lane; i < end; i += 32) {
            float e = __expf(g_alpha[i] - mx);
            g_alpha[i] = e;
            sum += e;
        }
#pragma unroll
        for (int o = 16; o; o >>= 1) sum += __shfl_xor_sync(0xffffffffu, sum, o);
        float inv = 1.f / sum;
        for (int i = beg + lane; i < end; i += 32)
            g_alpha[i] *= inv;
    }
}

// ---------------- CSR gather segment-sum, fp16 rows -------------------------
template<bool IDX2, bool SRC_SCALE, bool PAIRW, bool FINAL>
__global__ void gather_kernel(const __half* __restrict__ src,
                              void* __restrict__ dstv,
                              const void* __restrict__ csrv,
                              const int* __restrict__ off,
                              const float* __restrict__ sscale,
                              const float* __restrict__ pw,
                              const float* __restrict__ oscale,
                              int nrows) {
    int row = blockIdx.x * (blockDim.x >> 5) + (threadIdx.x >> 5);
    if (row >= nrows) return;
    int lane = threadIdx.x & 31;
    int half = lane >> 4;
    int hl = lane & 15;
    int beg = __ldg(&off[row]), end = __ldg(&off[row + 1]);
    const uint4* s4 = (const uint4*)src;
    const int*  csr1 = (const int*)csrv;
    const int2* csr2 = (const int2*)csrv;
    float acc[8];
#pragma unroll
    for (int c = 0; c < 8; c++) acc[c] = 0.f;

    int i = beg;
    for (; i + 8 <= end; i += 8) {
        int idx[4]; float w[4]; uint4 r[4];
#pragma unroll
        for (int u = 0; u < 4; u++)
            idx[u] = IDX2 ? __ldg(&csr2[i + 2 * u + half]).x
                          : __ldg(&csr1[i + 2 * u + half]);
#pragma unroll
        for (int u = 0; u < 4; u++) {
            w[u] = 1.f;
            if (SRC_SCALE) w[u] *= __ldg(&sscale[idx[u]]);
            if (PAIRW)     w[u] *= __ldg(&pw[i + 2 * u + half]);
        }
#pragma unroll
        for (int u = 0; u < 4; u++) r[u] = __ldg(&s4[(size_t)idx[u] * 16 + hl]);
#pragma unroll
        for (int u = 0; u < 4; u++) {
            float2 f0 = __half22float2(*(__half2*)&r[u].x);
            float2 f1 = __half22float2(*(__half2*)&r[u].y);
            float2 f2 = __half22float2(*(__half2*)&r[u].z);
            float2 f3 = __half22float2(*(__half2*)&r[u].w);
            if (SRC_SCALE || PAIRW) {
                acc[0] = fmaf(w[u], f0.x, acc[0]); acc[1] = fmaf(w[u], f0.y, acc[1]);
                acc[2] = fmaf(w[u], f1.x, acc[2]); acc[3] = fmaf(w[u], f1.y, acc[3]);
                acc[4] = fmaf(w[u], f2.x, acc[4]); acc[5] = fmaf(w[u], f2.y, acc[5]);
                acc[6] = fmaf(w[u], f3.x, acc[6]); acc[7] = fmaf(w[u], f3.y, acc[7]);
            } else {
                acc[0] += f0.x; acc[1] += f0.y; acc[2] += f1.x; acc[3] += f1.y;
                acc[4] += f2.x; acc[5] += f2.y; acc[6] += f3.x; acc[7] += f3.y;
            }
        }
    }
    for (; i < end; i += 2) {
        int j = i + half;
        if (j < end) {
            int idx = IDX2 ? __ldg(&csr2[j]).x : __ldg(&csr1[j]);
            float w = 1.f;
            if (SRC_SCALE) w *= __ldg(&sscale[idx]);
            if (PAIRW)     w *= __ldg(&pw[j]);
            uint4 r = __ldg(&s4[(size_t)idx * 16 + hl]);
            float2 f0 = __half22float2(*(__half2*)&r.x);
            float2 f1 = __half22float2(*(__half2*)&r.y);
            float2 f2 = __half22float2(*(__half2*)&r.z);
            float2 f3 = __half22float2(*(__half2*)&r.w);
            acc[0] = fmaf(w, f0.x, acc[0]); acc[1] = fmaf(w, f0.y, acc[1]);
            acc[2] = fmaf(w, f1.x, acc[2]); acc[3] = fmaf(w, f1.y, acc[3]);
            acc[4] = fmaf(w, f2.x, acc[4]); acc[5] = fmaf(w, f2.y, acc[5]);
            acc[6] = fmaf(w, f3.x, acc[6]); acc[7] = fmaf(w, f3.y, acc[7]);
        }
    }
#pragma unroll
    for (int c = 0; c < 8; c++)
        acc[c] += __shfl_xor_sync(0xffffffffu, acc[c], 16);

    float os = oscale ? __ldg(&oscale[row]) : 1.f;
#pragma unroll
    for (int c = 0; c < 8; c++) acc[c] *= os;

    if (lane < 16) {
        if (FINAL) {
#pragma unroll
            for (int c = 0; c < 8; c++)
                acc[c] = acc[c] > 0.f ? acc[c] : expm1f(acc[c]);
            float* o = (float*)dstv + (size_t)row * C + hl * 8;
            *(float4*)o       = make_float4(acc[0], acc[1], acc[2], acc[3]);
            *(float4*)(o + 4) = make_float4(acc[4], acc[5], acc[6], acc[7]);
        } else {
            __half2 h0 = __floats2half2_rn(acc[0], acc[1]);
            __half2 h1 = __floats2half2_rn(acc[2], acc[3]);
            __half2 h2 = __floats2half2_rn(acc[4], acc[5]);
            __half2 h3 = __floats2half2_rn(acc[6], acc[7]);
            uint4 o;
            o.x = *(unsigned*)&h0; o.y = *(unsigned*)&h1;
            o.z = *(unsigned*)&h2; o.w = *(unsigned*)&h3;
            ((uint4*)dstv)[(size_t)row * 16 + hl] = o;
        }
    }
}

// ---------------- launch ------------------------------------------------------
extern "C" void kernel_launch(void* const* d_in, const int* in_sizes, int n_in,
                              void* d_out, int out_size) {
    const float* X      = (const float*)d_in[0];
    const int*   pair_v = (const int*)d_in[1];
    const int*   pair_e = (const int*)d_in[2];
    const int*   src_v  = (const int*)d_in[3];
    const float* Wt     = (const float*)d_in[4];
    const float* bt     = (const float*)d_in[5];
    const float* wsrc   = (const float*)d_in[6];
    const float* wdst   = (const float*)d_in[7];
    float* out = (float*)d_out;

    void *pH16, *pE, *pV, *ps, *pd, *pcv, *pce, *pov, *poe;
    void *pdvi, *pinvde, *pinvdv, *palpha, *pcsrvp, *pcsres;
    cudaGetSymbolAddress(&pH16, g_H16);
    cudaGetSymbolAddress(&pE,   g_Edge);
    cudaGetSymbolAddress(&pV,   g_Vert);
    cudaGetSymbolAddress(&ps,   g_s);
    cudaGetSymbolAddress(&pd,   g_d);
    cudaGetSymbolAddress(&pcv,  g_cnt_v);
    cudaGetSymbolAddress(&pce,  g_cnt_e);
    cudaGetSymbolAddress(&pov,  g_off_v);
    cudaGetSymbolAddress(&poe,  g_off_e);
    cudaGetSymbolAddress(&pdvi,   g_dvi);
    cudaGetSymbolAddress(&pinvde, g_inv_de);
    cudaGetSymbolAddress(&pinvdv, g_inv_dv);
    cudaGetSymbolAddress(&palpha, g_alpha);
    cudaGetSymbolAddress(&pcsrvp, g_csr_v_pack);
    cudaGetSymbolAddress(&pcsres, g_csr_e_src);

    const __half* H16    = (const __half*)pH16;
    __half*       Ebuf   = (__half*)pE;
    __half*       Vbuf   = (__half*)pV;
    const float*  dvi    = (const float*)pdvi;
    const float*  inv_de = (const float*)pinvde;
    const float*  inv_dv = (const float*)pinvdv;
    const float*  alpha  = (const float*)palpha;
    const int*    off_v  = (const int*)pov;
    const int*    off_e  = (const int*)poe;

    const int TB = 256;
    const int WPB = TB / 32;
    const int pair4Blocks = (PP / 4 + TB - 1) / TB;
    const int gemmBlocks = (NV + 127) / 128;
    const int eRowBlocks = (ME + WPB - 1) / WPB;
    const int vRowBlocks = (NV + WPB - 1) / WPB;

    // ---- one-time stream/event setup (host resources only; no device mem) ----
    static cudaStream_t sA = nullptr, sB = nullptr;
    static cudaEvent_t ev0 = nullptr, evA = nullptr, evF = nullptr,
                       evS = nullptr, evB = nullptr;
    if (sA == nullptr) {
        cudaStreamCreateWithFlags(&sA, cudaStreamNonBlocking);
        cudaStreamCreateWithFlags(&sB, cudaStreamNonBlocking);
        cudaEventCreateWithFlags(&ev0, cudaEventDisableTiming);
        cudaEventCreateWithFlags(&evA, cudaEventDisableTiming);
        cudaEventCreateWithFlags(&evF, cudaEventDisableTiming);
        cudaEventCreateWithFlags(&evS, cudaEventDisableTiming);
        cudaEventCreateWithFlags(&evB, cudaEventDisableTiming);
        cudaFuncSetAttribute(gemm_wmma_kernel,
                             cudaFuncAttributeMaxDynamicSharedMemorySize, 65536);
    }

    // ---- fork: chain A (GEMM + s,d) on sA --------------------------------------
    cudaEventRecord(ev0, 0);
    cudaStreamWaitEvent(sA, ev0, 0);
    prep_uw_kernel<<<1, C, 0, sA>>>(Wt, bt, wsrc, wdst);
    gemm_wmma_kernel<<<gemmBlocks, TB, 65536, sA>>>(X, Wt, bt, (__half*)pH16, NV);
    sd_kernel<<<(NV * 32 + TB - 1) / TB, TB, 0, sA>>>(X, (float*)ps, (float*)pd);
    cudaEventRecord(evA, sA);

    // ---- chain B (CSR build) on capture stream ---------------------------------
    cudaMemsetAsync(pcv, 0, NV * sizeof(int));
    cudaMemsetAsync(pce, 0, ME * sizeof(int));
    hist_kernel4<<<pair4Blocks, TB>>>((const int4*)pair_v, (const int4*)pair_e);
    scan_reduce_both<<<NBV + NBE, SCAN_B>>>();
    scan_partials_both<<<2, SCAN_B>>>();
    scan_apply_both<<<NBV + NBE, SCAN_B>>>();
    fill_kernel4<<<pair4Blocks, TB>>>((const int4*)pair_v, (const int4*)pair_e,
                                      (const int4*)src_v);
    cudaEventRecord(evF, 0);

    // ---- sB: P1..P3 need fill + GEMM -------------------------------------------
    cudaStreamWaitEvent(sB, evF, 0);
    cudaStreamWaitEvent(sB, evA, 0);
    // P1: Edge = Xe = inv_de * segsum_e( H16[v] * dvi[v] )
    gather_kernel<false, true, false, false><<<eRowBlocks, TB, 0, sB>>>(
        H16, Ebuf, pcsres, off_e, dvi, nullptr, inv_de, ME);
    // P2: Vert = Hs = dvi[v] * segsum_v( Edge[e] )
    gather_kernel<true, false, false, false><<<vRowBlocks, TB, 0, sB>>>(
        Ebuf, Vbuf, pcsrvp, off_v, nullptr, nullptr, dvi, NV);
    // P3: Edge = Xe1 = inv_de * segsum_e( Vert[v] )
    gather_kernel<false, false, false, false><<<eRowBlocks, TB, 0, sB>>>(
        Vbuf, Ebuf, pcsres, off_e, nullptr, nullptr, inv_de, ME);

    // ---- capture stream: softmax (after fill in-order; needs s,d) — overlaps P1-P3
    cudaStreamWaitEvent(0, evA, 0);
    softmax_kernel<<<vRowBlocks, TB>>>((const float*)ps, (const float*)pd);
    cudaEventRecord(evS, 0);

    // ---- sB: P4..P6 (P4 needs alpha) --------------------------------------------
    cudaStreamWaitEvent(sB, evS, 0);
    // P4: Vert = Xv1 = segsum_v( alpha_slot * Edge[e] )
    gather_kernel<true, false, true, false><<<vRowBlocks, TB, 0, sB>>>(
        Ebuf, Vbuf, pcsrvp, off_v, nullptr, alpha, nullptr, NV);
    // P5: Edge = Xe2 = inv_de * segsum_e( Vert[v] )
    gather_kernel<false, false, false, false><<<eRowBlocks, TB, 0, sB>>>(
        Vbuf, Ebuf, pcsres, off_e, nullptr, nullptr, inv_de, ME);
    // P6: out = elu( inv_dv * segsum_v( Edge[e] ) )  (fp32 out)
    gather_kernel<true, false, false, true><<<vRowBlocks, TB, 0, sB>>>(
        Ebuf, out, pcsrvp, off_v, nullptr, nullptr, inv_dv, NV);
    cudaEventRecord(evB, sB);

    // ---- join --------------------------------------------------------------------
    cudaStreamWaitEvent(0, evB, 0);
}